// round 11
// baseline (speedup 1.0000x reference)
#include <cuda_runtime.h>

#define NIMG      32
#define IMH       512
#define IMW       512
#define PATCH     13
#define OWIDTH    500
#define OHEIGHT   500
#define SW        8          // output cols per thread
#define SH        13         // output rows per band (last band: 6)
#define NBANDS    39         // 38*13 + 6 = 500 output rows
#define NSTRIPS   63         // ceil(500/8); last strip emits 4 cols
#define THREADS   64
#define NLOAD     20         // floats loaded per row per image (SW + 12)
#define EPSF      1e-5f

// per-(image,band) partials: [ccsum, S1, S2, S11, S22, S12]
__device__ float g_part[NIMG * NBANDS * 6];
__device__ unsigned int g_cnt[NIMG];   // zero-init; reset by finalizer each launch

__device__ __forceinline__ void load_row(const float* __restrict__ p,
                                         float v[NLOAD], bool tail) {
    const float4* q = reinterpret_cast<const float4*>(p);
#pragma unroll
    for (int i = 0; i < 5; i++) {
        if (tail && i == 4) {
            v[16] = v[17] = v[18] = v[19] = 0.f;
        } else {
            float4 t = __ldg(q + i);
            v[4*i+0] = t.x; v[4*i+1] = t.y; v[4*i+2] = t.z; v[4*i+3] = t.w;
        }
    }
}

// Add (ADD=true) or subtract the horizontal 13-tap sums of one input row into
// the per-thread 2D box accumulators for its SW output columns.
template<bool ADD>
__device__ __forceinline__ void accum_strip(float S0[SW], float S1[SW], float S2[SW],
                                            float S3[SW], float S4[SW],
                                            const float a[NLOAD], const float b[NLOAD]) {
    float h0 = 0.f, h1 = 0.f, h2 = 0.f, h3 = 0.f, h4 = 0.f;
#pragma unroll
    for (int k = 0; k < PATCH; k++) {
        float xa = a[k], xb = b[k];
        h0 += xa;
        h1 += xb;
        h2 = fmaf(xa, xa, h2);
        h3 = fmaf(xb, xb, h3);
        h4 = fmaf(xa, xb, h4);
    }
#pragma unroll
    for (int j = 0; j < SW; j++) {
        if (j > 0) {
            float xa = a[j + 12], xb = b[j + 12];
            float ya = a[j - 1],  yb = b[j - 1];
            h0 += xa - ya;
            h1 += xb - yb;
            h2 += fmaf(xa, xa, -(ya * ya));
            h3 += fmaf(xb, xb, -(yb * yb));
            h4 += fmaf(xa, xb, -(ya * yb));
        }
        if (ADD) { S0[j] += h0; S1[j] += h1; S2[j] += h2; S3[j] += h3; S4[j] += h4; }
        else     { S0[j] -= h0; S1[j] -= h1; S2[j] -= h2; S3[j] -= h3; S4[j] -= h4; }
    }
}

// Global-NCC partial sums over this thread's OWNED columns of one row.
__device__ __forceinline__ void accum_global(float gs[5], const float a[NLOAD],
                                             const float b[NLOAD], bool wide) {
    const int lim = wide ? 16 : SW;   // last strip owns cols 496..511
#pragma unroll
    for (int j = 0; j < 16; j++) {
        if (j >= lim) break;
        float xa = a[j], xb = b[j];
        gs[0] += xa; gs[1] += xb;
        gs[2] = fmaf(xa, xa, gs[2]);
        gs[3] = fmaf(xb, xb, gs[3]);
        gs[4] = fmaf(xa, xb, gs[4]);
    }
}

__global__ void __launch_bounds__(THREADS, 9)
ncc_fused_kernel(const float* __restrict__ x1, const float* __restrict__ x2,
                 float* __restrict__ out) {
    const int band = blockIdx.x;
    const int img  = blockIdx.y;
    const int t    = threadIdx.x;
    const bool active    = (t < NSTRIPS);
    const bool last_band = (band == NBANDS - 1);
    const bool wide      = (t == NSTRIPS - 1);
    const bool tail      = wide;                  // must not load cols >= 512

    const int c0 = t * SW;
    const int r0 = band * SH;                     // last band: r0 = 494
    const int Eb = (OHEIGHT - r0) < SH ? (OHEIGHT - r0) : SH;   // emitted rows
    int nv = OWIDTH - c0; if (nv > SW) nv = SW;   // <=0 never (t<63 guard via active)
    const int nvalid = nv;

    const float* __restrict__ b1 = x1 + (size_t)img * IMH * IMW;
    const float* __restrict__ b2 = x2 + (size_t)img * IMH * IMW;

    float S0[SW], S1[SW], S2[SW], S3[SW], S4[SW];
#pragma unroll
    for (int j = 0; j < SW; j++) { S0[j]=0.f; S1[j]=0.f; S2[j]=0.f; S3[j]=0.f; S4[j]=0.f; }
    float gs[5] = {0.f, 0.f, 0.f, 0.f, 0.f};
    float ccacc = 0.f;

    if (active) {
        float a[NLOAD], bb[NLOAD];

        // ---- init: first 13 input rows of the band.
        // Ownership for global sums: every band owns its 13 init rows
        // (bands 0..37 tile rows 0..493; band 38's init = 494..506);
        // the last band additionally owns its incoming rows 507..511.
#pragma unroll 1
        for (int k = 0; k < PATCH; k++) {
            const int row = r0 + k;
            load_row(b1 + (size_t)row * IMW + c0, a, tail);
            load_row(b2 + (size_t)row * IMW + c0, bb, tail);
            accum_strip<true>(S0, S1, S2, S3, S4, a, bb);
            accum_global(gs, a, bb, wide);
        }

        const float N169 = 169.0f;
        const float EPS2 = 169.0f * 169.0f * EPSF;

#pragma unroll 1
        for (int i = 0; i < Eb; i++) {
            const bool has_next = (i + 1 < Eb);

            // prefetch incoming input row before the emit math
            if (has_next) {
                const int rin = r0 + PATCH + i;
                load_row(b1 + (size_t)rin * IMW + c0, a, tail);
                load_row(b2 + (size_t)rin * IMW + c0, bb, tail);
            }

            // ---- emit cc for output row r0+i (unnormalized form):
            //   u = n^2 (v + eps) = n*s11 - s1^2 + n^2*eps
            //   A = n*s12 - s1*s2 ;  cc_unnorm = A * rsqrt(u1*u2)
            //   (the factor n=169 is folded into the final scale)
#pragma unroll
            for (int j = 0; j < SW; j++) {
                if (j < nvalid) {
                    float s1 = S0[j], s2 = S1[j];
                    float u1 = fmaf(S2[j], N169, EPS2) - s1 * s1;
                    float u2 = fmaf(S3[j], N169, EPS2) - s2 * s2;
                    float A  = fmaf(S4[j], N169, -(s1 * s2));
                    ccacc = fmaf(A, rsqrtf(u1 * u2), ccacc);
                }
            }

            if (has_next) {
                accum_strip<true>(S0, S1, S2, S3, S4, a, bb);
                // incoming rows (13+i >= SH=13 always) owned only by last band
                if (last_band)
                    accum_global(gs, a, bb, wide);

                // departing input row (cache-resident re-read; already counted)
                const int rout = r0 + i;
                load_row(b1 + (size_t)rout * IMW + c0, a, tail);
                load_row(b2 + (size_t)rout * IMW + c0, bb, tail);
                accum_strip<false>(S0, S1, S2, S3, S4, a, bb);
            }
        }
    }

    // ---- deterministic block reduction of (ccacc, gs[0..4])
    float vals[6] = {ccacc, gs[0], gs[1], gs[2], gs[3], gs[4]};
#pragma unroll
    for (int off = 16; off > 0; off >>= 1) {
#pragma unroll
        for (int q = 0; q < 6; q++)
            vals[q] += __shfl_down_sync(0xffffffffu, vals[q], off);
    }
    __shared__ float red[THREADS / 32][6];
    __shared__ bool  is_last;
    const int w = t >> 5, l = t & 31;
    if (l == 0) {
#pragma unroll
        for (int q = 0; q < 6; q++) red[w][q] = vals[q];
    }
    __syncthreads();
    if (t == 0) {
        float* dst = g_part + ((size_t)img * NBANDS + band) * 6;
#pragma unroll
        for (int q = 0; q < 6; q++)
            dst[q] = red[0][q] + red[1][q];
        __threadfence();
        unsigned old = atomicAdd(&g_cnt[img], 1u);
        is_last = (old == NBANDS - 1);
    }
    __syncthreads();

    // ---- last arriving block for this image finalizes (fixed-order sums)
    if (is_last) {
        __threadfence();
        __shared__ float comp[6];
        if (t < 6) {
            const float* src = g_part + (size_t)img * NBANDS * 6;
            float acc = 0.f;
#pragma unroll 1
            for (int k = 0; k < NBANDS; k++)
                acc += src[k * 6 + t];
            comp[t] = acc;
        }
        __syncthreads();
        if (t == 0) {
            const float ccsum = comp[0];
            const float s1 = comp[1], s2 = comp[2];
            const float s11 = comp[3], s22 = comp[4], s12 = comp[5];
            const float invN = 1.0f / (float)(IMH * IMW);
            const float m1 = s1 * invN;
            const float m2 = s2 * invN;
            const float v1 = fmaf(s11, invN, -(m1 * m1)) + EPSF;
            const float v2 = fmaf(s22, invN, -(m2 * m2)) + EPSF;
            const float g  = fmaf(s12, invN, -(m1 * m2)) * rsqrtf(v1 * v2);
            const float p  = ccsum * (1.0f / (500.0f * 500.0f));  // n folded out
            out[img] = 0.5f * g + 0.5f * p;
            g_cnt[img] = 0;   // reset for next launch / graph replay
        }
    }
}

extern "C" void kernel_launch(void* const* d_in, const int* in_sizes, int n_in,
                              void* d_out, int out_size) {
    const float* x1 = (const float*)d_in[0];
    const float* x2 = (const float*)d_in[1];
    float* out = (float*)d_out;

    dim3 grid(NBANDS, NIMG);
    ncc_fused_kernel<<<grid, THREADS>>>(x1, x2, out);
}

// round 12
// speedup vs baseline: 1.3064x; 1.3064x over previous
#include <cuda_runtime.h>

#define NIMG      32
#define IMH       512
#define IMW       512
#define PATCH     13
#define OWIDTH    500
#define OHEIGHT   500
#define SW        8          // output cols per thread
#define SH        14         // output rows per band (last band: 10)
#define NBANDS    36         // 35*14 + 10 = 500 output rows
#define NSTRIPS   63         // strips 0..62 active; strip 62 emits 4 cols
#define THREADS   64
#define NLOAD     20         // floats loaded per row per image (SW + 12)
#define EPSF      1e-5f

// per-(image,band) partials: [ccsum, S1, S2, S11, S22, S12]
__device__ float g_part[NIMG * NBANDS * 6];
__device__ unsigned int g_cnt[NIMG];   // zero-init; reset by finalizer each launch

__device__ __forceinline__ void load_row(const float* __restrict__ p,
                                         float v[NLOAD], bool tail) {
    const float4* q = reinterpret_cast<const float4*>(p);
#pragma unroll
    for (int i = 0; i < 5; i++) {
        if (tail && i == 4) {
            v[16] = v[17] = v[18] = v[19] = 0.f;
        } else {
            float4 t = __ldg(q + i);
            v[4*i+0] = t.x; v[4*i+1] = t.y; v[4*i+2] = t.z; v[4*i+3] = t.w;
        }
    }
}

// Add (ADD=true) or subtract the horizontal 13-tap sums of one input row into
// the per-thread 2D box accumulators for its SW output columns.
template<bool ADD>
__device__ __forceinline__ void accum_strip(float S0[SW], float S1[SW], float S2[SW],
                                            float S3[SW], float S4[SW],
                                            const float a[NLOAD], const float b[NLOAD]) {
    float h0 = 0.f, h1 = 0.f, h2 = 0.f, h3 = 0.f, h4 = 0.f;
#pragma unroll
    for (int k = 0; k < PATCH; k++) {
        float xa = a[k], xb = b[k];
        h0 += xa;
        h1 += xb;
        h2 = fmaf(xa, xa, h2);
        h3 = fmaf(xb, xb, h3);
        h4 = fmaf(xa, xb, h4);
    }
#pragma unroll
    for (int j = 0; j < SW; j++) {
        if (j > 0) {
            float xa = a[j + 12], xb = b[j + 12];
            float ya = a[j - 1],  yb = b[j - 1];
            h0 += xa - ya;
            h1 += xb - yb;
            h2 += fmaf(xa, xa, -(ya * ya));
            h3 += fmaf(xb, xb, -(yb * yb));
            h4 += fmaf(xa, xb, -(ya * yb));
        }
        if (ADD) { S0[j] += h0; S1[j] += h1; S2[j] += h2; S3[j] += h3; S4[j] += h4; }
        else     { S0[j] -= h0; S1[j] -= h1; S2[j] -= h2; S3[j] -= h3; S4[j] -= h4; }
    }
}

// Global-NCC partial sums over this thread's OWNED columns of one row.
__device__ __forceinline__ void accum_global(float gs[5], const float a[NLOAD],
                                             const float b[NLOAD], bool wide) {
    const int lim = wide ? 16 : SW;   // last strip owns cols 496..511
#pragma unroll
    for (int j = 0; j < 16; j++) {
        if (j >= lim) break;
        float xa = a[j], xb = b[j];
        gs[0] += xa; gs[1] += xb;
        gs[2] = fmaf(xa, xa, gs[2]);
        gs[3] = fmaf(xb, xb, gs[3]);
        gs[4] = fmaf(xa, xb, gs[4]);
    }
}

__global__ void __launch_bounds__(THREADS, 8)
ncc_fused_kernel(const float* __restrict__ x1, const float* __restrict__ x2,
                 float* __restrict__ out) {
    const int band = blockIdx.x;
    const int img  = blockIdx.y;
    const int t    = threadIdx.x;
    const bool active    = (t < NSTRIPS);
    const bool last_band = (band == NBANDS - 1);
    const bool wide      = (t == NSTRIPS - 1);
    const bool tail      = wide;                  // must not load cols >= 512

    const int c0 = t * SW;
    const int r0 = band * SH;                     // last band: r0 = 490
    const int Eb = (OHEIGHT - r0) < SH ? (OHEIGHT - r0) : SH;   // emitted rows
    int nv = OWIDTH - c0; if (nv > SW) nv = SW;
    const int nvalid = nv;

    float S0[SW], S1[SW], S2[SW], S3[SW], S4[SW];
#pragma unroll
    for (int j = 0; j < SW; j++) { S0[j]=0.f; S1[j]=0.f; S2[j]=0.f; S3[j]=0.f; S4[j]=0.f; }
    float gs[5] = {0.f, 0.f, 0.f, 0.f, 0.f};
    float ccacc = 0.f;

    const float N169 = 169.0f;
    const float EPS2 = 169.0f * 169.0f * EPSF;

    if (active) {
        float a[NLOAD], bb[NLOAD];

        // running pointers (replace per-event IMAD address chains)
        const float* p1 = x1 + (size_t)img * IMH * IMW + (size_t)r0 * IMW + c0;
        const float* p2 = x2 + (size_t)img * IMH * IMW + (size_t)r0 * IMW + c0;

        // ---- init: first 13 input rows of the band (all owned: 13 < SH=14;
        // each band's 14-row ownership = 13 init rows + its first incoming row;
        // the last band additionally owns all incoming rows up to 511)
#pragma unroll 1
        for (int k = 0; k < PATCH; k++) {
            load_row(p1, a, tail);
            load_row(p2, bb, tail);
            p1 += IMW; p2 += IMW;
            accum_strip<true>(S0, S1, S2, S3, S4, a, bb);
            accum_global(gs, a, bb, wide);
        }

        // after init: p1/p2 point at in-row r0+13; out pointers at r0
        const float* o1 = p1 - PATCH * IMW;
        const float* o2 = p2 - PATCH * IMW;

        // ---- steady loop, branch-free body (last emit peeled)
#pragma unroll 1
        for (int i = 0; i < Eb - 1; i++) {
            // prefetch incoming input row before the emit math
            load_row(p1, a, tail);
            load_row(p2, bb, tail);
            p1 += IMW; p2 += IMW;

            // ---- emit cc for output row r0+i (unnormalized form):
            //   u = n^2 (v + eps) = n*s11 - s1^2 + n^2*eps
            //   A = n*s12 - s1*s2 ;  cc_unnorm = A * rsqrt(u1*u2)
            //   (the factor n=169 is folded into the final scale)
#pragma unroll
            for (int j = 0; j < SW; j++) {
                if (j < nvalid) {
                    float s1 = S0[j], s2 = S1[j];
                    float u1 = fmaf(S2[j], N169, EPS2) - s1 * s1;
                    float u2 = fmaf(S3[j], N169, EPS2) - s2 * s2;
                    float A  = fmaf(S4[j], N169, -(s1 * s2));
                    ccacc = fmaf(A, rsqrtf(u1 * u2), ccacc);
                }
            }

            accum_strip<true>(S0, S1, S2, S3, S4, a, bb);
            // incoming row owned iff still inside band's 14 owned rows (only
            // i==0: row r0+13), or anywhere in the last band
            if ((PATCH + i < SH) || last_band)
                accum_global(gs, a, bb, wide);

            // departing input row (cache-resident re-read; already counted)
            load_row(o1, a, tail);
            load_row(o2, bb, tail);
            o1 += IMW; o2 += IMW;
            accum_strip<false>(S0, S1, S2, S3, S4, a, bb);
        }

        // ---- final output row (Eb-1)
#pragma unroll
        for (int j = 0; j < SW; j++) {
            if (j < nvalid) {
                float s1 = S0[j], s2 = S1[j];
                float u1 = fmaf(S2[j], N169, EPS2) - s1 * s1;
                float u2 = fmaf(S3[j], N169, EPS2) - s2 * s2;
                float A  = fmaf(S4[j], N169, -(s1 * s2));
                ccacc = fmaf(A, rsqrtf(u1 * u2), ccacc);
            }
        }
    }

    // ---- deterministic block reduction of (ccacc, gs[0..4])
    float vals[6] = {ccacc, gs[0], gs[1], gs[2], gs[3], gs[4]};
#pragma unroll
    for (int off = 16; off > 0; off >>= 1) {
#pragma unroll
        for (int q = 0; q < 6; q++)
            vals[q] += __shfl_down_sync(0xffffffffu, vals[q], off);
    }
    __shared__ float red[THREADS / 32][6];
    __shared__ bool  is_last;
    const int w = t >> 5, l = t & 31;
    if (l == 0) {
#pragma unroll
        for (int q = 0; q < 6; q++) red[w][q] = vals[q];
    }
    __syncthreads();
    if (t == 0) {
        float* dst = g_part + ((size_t)img * NBANDS + band) * 6;
#pragma unroll
        for (int q = 0; q < 6; q++)
            dst[q] = red[0][q] + red[1][q];
        __threadfence();
        unsigned old = atomicAdd(&g_cnt[img], 1u);
        is_last = (old == NBANDS - 1);
    }
    __syncthreads();

    // ---- last arriving block for this image finalizes (fixed-order sums)
    if (is_last) {
        __threadfence();
        __shared__ float comp[6];
        if (t < 6) {
            const float* src = g_part + (size_t)img * NBANDS * 6;
            float acc = 0.f;
#pragma unroll 1
            for (int k = 0; k < NBANDS; k++)
                acc += src[k * 6 + t];
            comp[t] = acc;
        }
        __syncthreads();
        if (t == 0) {
            const float ccsum = comp[0];
            const float s1 = comp[1], s2 = comp[2];
            const float s11 = comp[3], s22 = comp[4], s12 = comp[5];
            const float invN = 1.0f / (float)(IMH * IMW);
            const float m1 = s1 * invN;
            const float m2 = s2 * invN;
            const float v1 = fmaf(s11, invN, -(m1 * m1)) + EPSF;
            const float v2 = fmaf(s22, invN, -(m2 * m2)) + EPSF;
            const float g  = fmaf(s12, invN, -(m1 * m2)) * rsqrtf(v1 * v2);
            const float p  = ccsum * (1.0f / (500.0f * 500.0f));  // n folded out
            out[img] = 0.5f * g + 0.5f * p;
            g_cnt[img] = 0;   // reset for next launch / graph replay
        }
    }
}

extern "C" void kernel_launch(void* const* d_in, const int* in_sizes, int n_in,
                              void* d_out, int out_size) {
    const float* x1 = (const float*)d_in[0];
    const float* x2 = (const float*)d_in[1];
    float* out = (float*)d_out;

    dim3 grid(NBANDS, NIMG);
    ncc_fused_kernel<<<grid, THREADS>>>(x1, x2, out);
}

// round 13
// speedup vs baseline: 1.3367x; 1.0232x over previous
#include <cuda_runtime.h>

#define NIMG      32
#define IMH       512
#define IMW       512
#define PATCH     13
#define OWIDTH    500
#define OHEIGHT   500
#define SW        8          // output cols per thread
#define SH        14         // output rows per band (last band: 10)
#define NBANDS    36         // 35*14 + 10 = 500 output rows
#define NSTRIPS   63         // strips 0..62 active; strip 62 emits 4 cols
#define THREADS   64
#define NLOAD     20         // floats loaded per row per image (SW + 12)
#define EPSF      1e-5f

// per-(image,band) partials: [ccsum, S1, S2, S11, S22, S12]
__device__ float g_part[NIMG * NBANDS * 6];
__device__ unsigned int g_cnt[NIMG];   // zero-init; reset by finalizer each launch

// single-instruction MUFU rsqrt regardless of fast-math flags
__device__ __forceinline__ float rsqrt_approx(float x) {
    float y;
    asm("rsqrt.approx.f32 %0, %1;" : "=f"(y) : "f"(x));
    return y;
}

__device__ __forceinline__ void load_row(const float* __restrict__ p,
                                         float v[NLOAD], bool tail) {
    const float4* q = reinterpret_cast<const float4*>(p);
#pragma unroll
    for (int i = 0; i < 5; i++) {
        if (tail && i == 4) {
            v[16] = v[17] = v[18] = v[19] = 0.f;
        } else {
            float4 t = __ldg(q + i);
            v[4*i+0] = t.x; v[4*i+1] = t.y; v[4*i+2] = t.z; v[4*i+3] = t.w;
        }
    }
}

// Add (ADD=true) or subtract the horizontal 13-tap sums of one input row into
// the per-thread 2D box accumulators. Rolling update uses the d/s identities:
//   x^2 - y^2 = (x-y)(x+y)
//   xa*xb - ya*yb = 0.5*((xa+ya)(xb-yb) + (xa-ya)(xb+yb))
template<bool ADD>
__device__ __forceinline__ void accum_strip(float S0[SW], float S1[SW], float S2[SW],
                                            float S3[SW], float S4[SW],
                                            const float a[NLOAD], const float b[NLOAD]) {
    float h0 = 0.f, h1 = 0.f, h2 = 0.f, h3 = 0.f, h4 = 0.f;
#pragma unroll
    for (int k = 0; k < PATCH; k++) {
        float xa = a[k], xb = b[k];
        h0 += xa;
        h1 += xb;
        h2 = fmaf(xa, xa, h2);
        h3 = fmaf(xb, xb, h3);
        h4 = fmaf(xa, xb, h4);
    }
#pragma unroll
    for (int j = 0; j < SW; j++) {
        if (j > 0) {
            float xa = a[j + 12], xb = b[j + 12];
            float ya = a[j - 1],  yb = b[j - 1];
            float da = xa - ya, sa = xa + ya;
            float db = xb - yb, sb = xb + yb;
            h0 += da;
            h1 += db;
            h2 = fmaf(da, sa, h2);
            h3 = fmaf(db, sb, h3);
            float u = sa * db;
            u = fmaf(da, sb, u);
            h4 = fmaf(0.5f, u, h4);
        }
        if (ADD) { S0[j] += h0; S1[j] += h1; S2[j] += h2; S3[j] += h3; S4[j] += h4; }
        else     { S0[j] -= h0; S1[j] -= h1; S2[j] -= h2; S3[j] -= h3; S4[j] -= h4; }
    }
}

// Global-NCC partial sums over this thread's OWNED columns of one row.
__device__ __forceinline__ void accum_global(float gs[5], const float a[NLOAD],
                                             const float b[NLOAD], bool wide) {
    const int lim = wide ? 16 : SW;   // last strip owns cols 496..511
#pragma unroll
    for (int j = 0; j < 16; j++) {
        if (j >= lim) break;
        float xa = a[j], xb = b[j];
        gs[0] += xa; gs[1] += xb;
        gs[2] = fmaf(xa, xa, gs[2]);
        gs[3] = fmaf(xb, xb, gs[3]);
        gs[4] = fmaf(xa, xb, gs[4]);
    }
}

__global__ void __launch_bounds__(THREADS, 8)
ncc_fused_kernel(const float* __restrict__ x1, const float* __restrict__ x2,
                 float* __restrict__ out) {
    const int band = blockIdx.x;
    const int img  = blockIdx.y;
    const int t    = threadIdx.x;
    const bool active    = (t < NSTRIPS);
    const bool last_band = (band == NBANDS - 1);
    const bool wide      = (t == NSTRIPS - 1);
    const bool tail      = wide;                  // must not load cols >= 512

    const int c0 = t * SW;
    const int r0 = band * SH;                     // last band: r0 = 490
    const int Eb = (OHEIGHT - r0) < SH ? (OHEIGHT - r0) : SH;   // emitted rows
    int nv = OWIDTH - c0; if (nv > SW) nv = SW;
    const int nvalid = nv;

    float S0[SW], S1[SW], S2[SW], S3[SW], S4[SW];
#pragma unroll
    for (int j = 0; j < SW; j++) { S0[j]=0.f; S1[j]=0.f; S2[j]=0.f; S3[j]=0.f; S4[j]=0.f; }
    float gs[5] = {0.f, 0.f, 0.f, 0.f, 0.f};
    float ccacc = 0.f;

    const float N169 = 169.0f;
    const float EPS2 = 169.0f * 169.0f * EPSF;

    if (active) {
        float a[NLOAD], bb[NLOAD];

        // running pointers (replace per-event IMAD address chains)
        const float* p1 = x1 + (size_t)img * IMH * IMW + (size_t)r0 * IMW + c0;
        const float* p2 = x2 + (size_t)img * IMH * IMW + (size_t)r0 * IMW + c0;

        // ---- init: first 13 input rows of the band (all owned: 13 < SH=14;
        // each band's 14-row ownership = 13 init rows + its first incoming row;
        // the last band additionally owns all incoming rows up to 511)
#pragma unroll 1
        for (int k = 0; k < PATCH; k++) {
            load_row(p1, a, tail);
            load_row(p2, bb, tail);
            p1 += IMW; p2 += IMW;
            accum_strip<true>(S0, S1, S2, S3, S4, a, bb);
            accum_global(gs, a, bb, wide);
        }

        // after init: p1/p2 point at in-row r0+13; out pointers at r0
        const float* o1 = p1 - PATCH * IMW;
        const float* o2 = p2 - PATCH * IMW;

        // ---- steady loop, branch-free body (last emit peeled)
#pragma unroll 1
        for (int i = 0; i < Eb - 1; i++) {
            // prefetch incoming input row before the emit math
            load_row(p1, a, tail);
            load_row(p2, bb, tail);
            p1 += IMW; p2 += IMW;

            // ---- emit cc for output row r0+i (unnormalized form):
            //   u = n^2 (v + eps) = n*s11 - s1^2 + n^2*eps
            //   A = n*s12 - s1*s2 ;  cc_unnorm = A * rsqrt(u1*u2)
            //   (the factor n=169 is folded into the final scale)
#pragma unroll
            for (int j = 0; j < SW; j++) {
                if (j < nvalid) {
                    float s1 = S0[j], s2 = S1[j];
                    float u1 = fmaf(S2[j], N169, EPS2) - s1 * s1;
                    float u2 = fmaf(S3[j], N169, EPS2) - s2 * s2;
                    float A  = fmaf(S4[j], N169, -(s1 * s2));
                    ccacc = fmaf(A, rsqrt_approx(u1 * u2), ccacc);
                }
            }

            accum_strip<true>(S0, S1, S2, S3, S4, a, bb);
            // incoming row owned iff still inside band's 14 owned rows (only
            // i==0: row r0+13), or anywhere in the last band
            if ((PATCH + i < SH) || last_band)
                accum_global(gs, a, bb, wide);

            // departing input row (cache-resident re-read; already counted)
            load_row(o1, a, tail);
            load_row(o2, bb, tail);
            o1 += IMW; o2 += IMW;
            accum_strip<false>(S0, S1, S2, S3, S4, a, bb);
        }

        // ---- final output row (Eb-1)
#pragma unroll
        for (int j = 0; j < SW; j++) {
            if (j < nvalid) {
                float s1 = S0[j], s2 = S1[j];
                float u1 = fmaf(S2[j], N169, EPS2) - s1 * s1;
                float u2 = fmaf(S3[j], N169, EPS2) - s2 * s2;
                float A  = fmaf(S4[j], N169, -(s1 * s2));
                ccacc = fmaf(A, rsqrt_approx(u1 * u2), ccacc);
            }
        }
    }

    // ---- deterministic block reduction of (ccacc, gs[0..4])
    float vals[6] = {ccacc, gs[0], gs[1], gs[2], gs[3], gs[4]};
#pragma unroll
    for (int off = 16; off > 0; off >>= 1) {
#pragma unroll
        for (int q = 0; q < 6; q++)
            vals[q] += __shfl_down_sync(0xffffffffu, vals[q], off);
    }
    __shared__ float red[THREADS / 32][6];
    __shared__ bool  is_last;
    const int w = t >> 5, l = t & 31;
    if (l == 0) {
#pragma unroll
        for (int q = 0; q < 6; q++) red[w][q] = vals[q];
    }
    __syncthreads();
    if (t == 0) {
        float* dst = g_part + ((size_t)img * NBANDS + band) * 6;
#pragma unroll
        for (int q = 0; q < 6; q++)
            dst[q] = red[0][q] + red[1][q];
        __threadfence();
        unsigned old = atomicAdd(&g_cnt[img], 1u);
        is_last = (old == NBANDS - 1);
    }
    __syncthreads();

    // ---- last arriving block for this image finalizes (fixed-order sums)
    if (is_last) {
        __threadfence();
        __shared__ float comp[6];
        if (t < 6) {
            const float* src = g_part + (size_t)img * NBANDS * 6;
            float acc = 0.f;
#pragma unroll 1
            for (int k = 0; k < NBANDS; k++)
                acc += src[k * 6 + t];
            comp[t] = acc;
        }
        __syncthreads();
        if (t == 0) {
            const float ccsum = comp[0];
            const float s1 = comp[1], s2 = comp[2];
            const float s11 = comp[3], s22 = comp[4], s12 = comp[5];
            const float invN = 1.0f / (float)(IMH * IMW);
            const float m1 = s1 * invN;
            const float m2 = s2 * invN;
            const float v1 = fmaf(s11, invN, -(m1 * m1)) + EPSF;
            const float v2 = fmaf(s22, invN, -(m2 * m2)) + EPSF;
            const float g  = fmaf(s12, invN, -(m1 * m2)) * rsqrtf(v1 * v2);
            const float p  = ccsum * (1.0f / (500.0f * 500.0f));  // n folded out
            out[img] = 0.5f * g + 0.5f * p;
            g_cnt[img] = 0;   // reset for next launch / graph replay
        }
    }
}

extern "C" void kernel_launch(void* const* d_in, const int* in_sizes, int n_in,
                              void* d_out, int out_size) {
    const float* x1 = (const float*)d_in[0];
    const float* x2 = (const float*)d_in[1];
    float* out = (float*)d_out;

    dim3 grid(NBANDS, NIMG);
    ncc_fused_kernel<<<grid, THREADS>>>(x1, x2, out);
}